// round 4
// baseline (speedup 1.0000x reference)
#include <cuda_runtime.h>
#include <cstdint>

#define NSEG   8
#define TPB1   512
#define TPB2   512
#define LCAND  8
#define KSEL   100
#define SEGBUF 128
#define NCOMB  (NSEG * SEGBUF)   // 1024
#define BMAX   256

// Scratch (allocation-free rule: __device__ globals)
__device__ unsigned long long g_seg[BMAX * NSEG * SEGBUF];  // 2 MB
__device__ float g_exps[BMAX * KSEL];
__device__ int   g_inds[BMAX * KSEL];

// Order-preserving float->uint key: bigger float => bigger key.
__device__ __forceinline__ unsigned fkey(float f) {
    unsigned u = __float_as_uint(f);
    return u ^ (unsigned)(((int)u >> 31) | 0x80000000);
}
__device__ __forceinline__ float fkey_inv(unsigned kk) {
    unsigned u = (kk & 0x80000000u) ? (kk ^ 0x80000000u) : ~kk;
    return __uint_as_float(u);
}

// ---------------------------------------------------------------------------
// Kernel 1: per-(row, segment) exact top-100 -> unsorted qualifiers in g_seg
// ---------------------------------------------------------------------------
__global__ __launch_bounds__(TPB1)
void topk_seg_kernel(const float* __restrict__ logits, int V) {
    const int b   = blockIdx.x;
    const int s   = blockIdx.y;
    const int tid = threadIdx.x;
    const int segLen = (V + NSEG - 1) / NSEG;
    const int seg0 = s * segLen;
    const int seg1 = min(V, seg0 + segLen);
    const float* row = logits + (size_t)b * V;

    // ---- Phase 1: per-thread top-8 composites (key<<32 | ~idx) ----
    unsigned long long c[LCAND];
#pragma unroll
    for (int j = 0; j < LCAND; j++) c[j] = 0ull;
    unsigned long long cmin = 0ull;
    unsigned cminHi = 0u;

    auto insert = [&](unsigned kk, int idx) {
        unsigned long long comp =
            ((unsigned long long)kk << 32) | (unsigned)(0xFFFFFFFFu - (unsigned)idx);
        if (comp > cmin) {
            bool done = false;
#pragma unroll
            for (int j = 0; j < LCAND; j++)
                if (!done && c[j] == cmin) { c[j] = comp; done = true; }
            unsigned long long m = c[0];
#pragma unroll
            for (int j = 1; j < LCAND; j++) m = (c[j] < m) ? c[j] : m;
            cmin = m;
            cminHi = (unsigned)(m >> 32);
        }
    };

    if (((seg0 | seg1) & 3) == 0) {
        const float4* r4 = (const float4*)(row + seg0);
        const int n4 = (seg1 - seg0) >> 2;
        for (int i = tid; i < n4; i += TPB1) {
            float4 v = r4[i];
            const int base = seg0 + i * 4;
            float vv[4] = {v.x, v.y, v.z, v.w};
#pragma unroll
            for (int q = 0; q < 4; q++) {
                unsigned kk = fkey(vv[q]);
                if (kk >= cminHi) insert(kk, base + q);   // rare path
            }
        }
    } else {
        for (int i = seg0 + tid; i < seg1; i += TPB1) {
            unsigned kk = fkey(row[i]);
            if (kk >= cminHi) insert(kk, i);
        }
    }

    // ---- Phase 2: exact 100th-largest key via 32-step bitwise search ----
    __shared__ int s_part[TPB1 / 32];
    __shared__ unsigned s_nc;

    const int wid  = tid >> 5;
    const int lane = tid & 31;

    unsigned keys[LCAND];
#pragma unroll
    for (int j = 0; j < LCAND; j++) keys[j] = (unsigned)(c[j] >> 32);

    unsigned X = 0;
    for (int bit = 31; bit >= 0; --bit) {
        unsigned trial = X | (1u << bit);
        int local = 0;
#pragma unroll
        for (int j = 0; j < LCAND; j++) local += (keys[j] >= trial);
#pragma unroll
        for (int off = 16; off; off >>= 1)
            local += __shfl_down_sync(0xffffffffu, local, off);
        if (lane == 0) s_part[wid] = local;
        __syncthreads();
        int cnt = 0;
#pragma unroll
        for (int w = 0; w < TPB1 / 32; w++) cnt += s_part[w];
        __syncthreads();
        if (cnt >= KSEL) X = trial;
    }
    // X = max key with count(key >= X) >= 100

    // ---- Phase 3: dump qualifiers (unsorted) to global, pad to SEGBUF ----
    if (tid == 0) s_nc = 0;
    __syncthreads();

    unsigned long long* dst = g_seg + (size_t)(b * NSEG + s) * SEGBUF;
#pragma unroll
    for (int j = 0; j < LCAND; j++) {
        if (keys[j] >= X && c[j] != 0ull) {
            unsigned p = atomicAdd(&s_nc, 1u);
            if (p < SEGBUF) dst[p] = c[j];
        }
    }
    __syncthreads();
    int n = min((int)s_nc, SEGBUF);
    for (int t = n + tid; t < SEGBUF; t += TPB1) dst[t] = 0ull;
}

// ---------------------------------------------------------------------------
// Kernel 2: per-row merge of 8 segment top-100s -> sorted top-100 + exps
// ---------------------------------------------------------------------------
__global__ __launch_bounds__(TPB2)
void combine_kernel(const float* __restrict__ sp) {
    const int b   = blockIdx.x;
    const int tid = threadIdx.x;

    __shared__ int s_part[TPB2 / 32];
    __shared__ unsigned s_nc;
    __shared__ unsigned long long s_cand[256];

    const unsigned long long* src = g_seg + (size_t)b * NCOMB;
    unsigned long long m0 = src[tid];
    unsigned long long m1 = src[tid + TPB2];
    unsigned k0 = (unsigned)(m0 >> 32);
    unsigned k1 = (unsigned)(m1 >> 32);

    const int wid  = tid >> 5;
    const int lane = tid & 31;

    unsigned X = 0;
    for (int bit = 31; bit >= 0; --bit) {
        unsigned trial = X | (1u << bit);
        int local = (k0 >= trial) + (k1 >= trial);
#pragma unroll
        for (int off = 16; off; off >>= 1)
            local += __shfl_down_sync(0xffffffffu, local, off);
        if (lane == 0) s_part[wid] = local;
        __syncthreads();
        int cnt = 0;
#pragma unroll
        for (int w = 0; w < TPB2 / 32; w++) cnt += s_part[w];
        __syncthreads();
        if (cnt >= KSEL) X = trial;
    }

    if (tid == 0) s_nc = 0;
    __syncthreads();
    if (k0 >= X && m0 != 0ull) {
        unsigned p = atomicAdd(&s_nc, 1u);
        if (p < 256) s_cand[p] = m0;
    }
    if (k1 >= X && m1 != 0ull) {
        unsigned p = atomicAdd(&s_nc, 1u);
        if (p < 256) s_cand[p] = m1;
    }
    __syncthreads();
    int n = min((int)s_nc, 256);
    for (int t = n + tid; t < 256; t += TPB2) s_cand[t] = 0ull;
    __syncthreads();

    // Bitonic sort 256, descending (composites unique; 0-pads sink to end)
    for (int ksz = 2; ksz <= 256; ksz <<= 1) {
        for (int j = ksz >> 1; j > 0; j >>= 1) {
            if (tid < 256) {
                int ixj = tid ^ j;
                if (ixj > tid) {
                    bool desc = ((tid & ksz) == 0);
                    unsigned long long a = s_cand[tid], bb = s_cand[ixj];
                    if (desc ? (a < bb) : (a > bb)) {
                        s_cand[tid] = bb;
                        s_cand[ixj] = a;
                    }
                }
            }
            __syncthreads();
        }
    }

    // Emit sorted top-100 indices + exp terms (parallel expf)
    if (tid < KSEL) {
        unsigned long long comp = s_cand[tid];
        float val = fkey_inv((unsigned)(comp >> 32));
        int   idx = (int)(0xFFFFFFFFu - (unsigned)(comp & 0xFFFFFFFFu));
        g_inds[b * KSEL + tid] = idx;

        float v0 = fkey_inv((unsigned)(s_cand[0] >> 32));
        int   k  = min(max((int)sp[b * 3 + 0], 1), KSEL);
        float T  = sp[b * 3 + 2];
        float e  = (tid < k) ? expf(val / T - v0 / T) : 0.0f;
        g_exps[b * KSEL + tid] = e;
    }
}

// ---------------------------------------------------------------------------
// Kernel 3: cross-row min + top-p + median-token pick (no transcendentals)
// Output written as float32 (tokens exactly representable).
// ---------------------------------------------------------------------------
__global__ void sample_kernel(const float* __restrict__ sp, int B,
                              float* __restrict__ out) {
    const int b = threadIdx.x;
    __shared__ float s_p0[1024];

    float S = 0.f, topp = 0.f;
    int k = 0;
    const float* e = g_exps + b * KSEL;

    if (b < B) {
        k    = min(max((int)sp[b * 3 + 0], 1), KSEL);
        topp = sp[b * 3 + 1];
        for (int i = 0; i < k; i++) S += e[i];
        s_p0[b] = 1.0f / S;           // probs[b,0] : per-row min of csum
    } else {
        s_p0[b] = 3.4e38f;
    }
    __syncthreads();

    // jnp.min(csum) over the full matrix = min_b probs[b,0]
    float m = s_p0[0];
    for (int i = 1; i < B; i++) m = fminf(m, s_p0[i]);

    if (b < B) {
        float eff  = fmaxf(m, topp);
        float invS = 1.0f / S;

        // top-p: survivors are a prefix (csum nondecreasing); pos 0 kept
        float csum = 0.f, S2 = 0.f;
        int ns = 0;
        for (int i = 0; i < k; i++) {
            float ei = e[i];
            csum += ei * invS;
            if (i > 0 && csum > eff) break;
            S2 += ei;
            ns++;
        }

        // second softmax cumsum; counts = #{csum2 < 0.5}
        float invS2 = 1.0f / S2;
        float c2 = 0.f;
        int cnt = 0;
        for (int i = 0; i < ns; i++) {
            c2 += e[i] * invS2;
            if (0.5f > c2) cnt++;
        }
        if (cnt > ns - 1) cnt = ns - 1;
        out[b] = (float)g_inds[b * KSEL + cnt];
    }
}

// ---------------------------------------------------------------------------
extern "C" void kernel_launch(void* const* d_in, const int* in_sizes, int n_in,
                              void* d_out, int out_size) {
    // Hedge on input ordering: sampling_params is the small (B*3) tensor.
    int li = 0, si = 1;
    if (n_in >= 2 && in_sizes[0] < in_sizes[1]) { li = 1; si = 0; }
    const float* logits = (const float*)d_in[li];
    const float* sp     = (const float*)d_in[si];
    int B = in_sizes[si] / 3;
    int V = in_sizes[li] / B;

    dim3 g1(B, NSEG);
    topk_seg_kernel<<<g1, TPB1>>>(logits, V);
    combine_kernel<<<B, TPB2>>>(sp);

    int nthr = ((B + 31) / 32) * 32;
    if (nthr > 1024) nthr = 1024;
    sample_kernel<<<1, nthr>>>(sp, B, (float*)d_out);
}

// round 5
// speedup vs baseline: 2.1731x; 2.1731x over previous
#include <cuda_runtime.h>
#include <cstdint>

#define KSEL   100
#define BMAX   256
#define CAP    2048          // per-row candidate capacity
#define NSEGF  32            // filter segments per row
#define TPBF   256           // filter block
#define TPBS   512           // select block
#define T0     8.3f          // filter threshold (fallback makes this safe)

// Scratch (__device__ globals; no allocation allowed)
__device__ int                g_cnt[BMAX];
__device__ unsigned long long g_buf[BMAX * CAP];   // 4 MB
__device__ float              g_exps[BMAX * KSEL];
__device__ int                g_inds[BMAX * KSEL];

// Order-preserving float->uint key: bigger float => bigger key.
__device__ __forceinline__ unsigned fkey(float f) {
    unsigned u = __float_as_uint(f);
    return u ^ (unsigned)(((int)u >> 31) | 0x80000000);
}
__device__ __forceinline__ float fkey_inv(unsigned kk) {
    unsigned u = (kk & 0x80000000u) ? (kk ^ 0x80000000u) : ~kk;
    return __uint_as_float(u);
}

// ---------------------------------------------------------------------------
__global__ void zero_kernel() {
    if (threadIdx.x < BMAX) g_cnt[threadIdx.x] = 0;
}

// ---------------------------------------------------------------------------
// Kernel 1: threshold filter. One compare per element; rare atomic push.
// ---------------------------------------------------------------------------
__global__ __launch_bounds__(TPBF)
void filter_kernel(const float* __restrict__ logits, int V) {
    const int b   = blockIdx.x;
    const int s   = blockIdx.y;
    const int tid = threadIdx.x;
    const float* row = logits + (size_t)b * V;

    const int V4 = V >> 2;
    const int segLen4 = (V4 + NSEGF - 1) / NSEGF;
    const int s0 = s * segLen4;
    const int s1 = min(V4, s0 + segLen4);

    const float4* r4 = (const float4*)row;
    unsigned long long* buf = g_buf + (size_t)b * CAP;

    for (int i = s0 + tid; i < s1; i += TPBF) {
        float4 v = r4[i];
        float m = fmaxf(fmaxf(v.x, v.y), fmaxf(v.z, v.w));
        if (m > T0) {                           // rare (~1% of quads)
            const int base = i * 4;
            float vv[4] = {v.x, v.y, v.z, v.w};
#pragma unroll
            for (int q = 0; q < 4; q++) {
                if (vv[q] > T0) {
                    int p = atomicAdd(&g_cnt[b], 1);
                    if (p < CAP) {
                        unsigned long long comp =
                            ((unsigned long long)fkey(vv[q]) << 32) |
                            (unsigned)(0xFFFFFFFFu - (unsigned)(base + q));
                        buf[p] = comp;
                    }
                }
            }
        }
    }

    // scalar tail (handled by last segment)
    if (s == NSEGF - 1) {
        for (int i = V4 * 4 + tid; i < V; i += TPBF) {
            float x = row[i];
            if (x > T0) {
                int p = atomicAdd(&g_cnt[b], 1);
                if (p < CAP) {
                    buf[p] = ((unsigned long long)fkey(x) << 32) |
                             (unsigned)(0xFFFFFFFFu - (unsigned)i);
                }
            }
        }
    }
}

// ---------------------------------------------------------------------------
// Block-wide count reduce helper state lives in shared inside select kernel.
// ---------------------------------------------------------------------------
__global__ __launch_bounds__(TPBS)
void select_kernel(const float* __restrict__ sp, int V,
                   const float* __restrict__ logits) {
    const int b   = blockIdx.x;
    const int tid = threadIdx.x;
    const int wid  = tid >> 5;
    const int lane = tid & 31;

    __shared__ int s_part[TPBS / 32];
    __shared__ unsigned s_nc;
    __shared__ unsigned long long s_cand[256];

    const int n = g_cnt[b];
    const float* row = logits + (size_t)b * V;

    unsigned X = 0;

    if (n >= KSEL && n <= CAP) {
        // ---- normal path: candidates from g_buf ----
        const unsigned long long* buf = g_buf + (size_t)b * CAP;
        unsigned long long c[4];
        unsigned keys[4];
#pragma unroll
        for (int j = 0; j < 4; j++) {
            int i = tid + j * TPBS;
            c[j] = (i < n) ? buf[i] : 0ull;
            keys[j] = (unsigned)(c[j] >> 32);
        }

        for (int bit = 31; bit >= 0; --bit) {
            unsigned trial = X | (1u << bit);
            int local = 0;
#pragma unroll
            for (int j = 0; j < 4; j++) local += (keys[j] >= trial);
#pragma unroll
            for (int off = 16; off; off >>= 1)
                local += __shfl_down_sync(0xffffffffu, local, off);
            if (lane == 0) s_part[wid] = local;
            __syncthreads();
            int cnt = 0;
#pragma unroll
            for (int w = 0; w < TPBS / 32; w++) cnt += s_part[w];
            __syncthreads();
            if (cnt >= KSEL) X = trial;
        }

        if (tid == 0) s_nc = 0;
        __syncthreads();
#pragma unroll
        for (int j = 0; j < 4; j++) {
            if (keys[j] >= X && c[j] != 0ull) {
                unsigned p = atomicAdd(&s_nc, 1u);
                if (p < 256) s_cand[p] = c[j];
            }
        }
        __syncthreads();
    } else {
        // ---- exact fallback: binary search by counting the full row ----
        for (int bit = 31; bit >= 0; --bit) {
            unsigned trial = X | (1u << bit);
            int local = 0;
            for (int i = tid; i < V; i += TPBS)
                local += (fkey(row[i]) >= trial);
#pragma unroll
            for (int off = 16; off; off >>= 1)
                local += __shfl_down_sync(0xffffffffu, local, off);
            if (lane == 0) s_part[wid] = local;
            __syncthreads();
            int cnt = 0;
#pragma unroll
            for (int w = 0; w < TPBS / 32; w++) cnt += s_part[w];
            __syncthreads();
            if (cnt >= KSEL) X = trial;
        }
        if (tid == 0) s_nc = 0;
        __syncthreads();
        for (int i = tid; i < V; i += TPBS) {
            unsigned kk = fkey(row[i]);
            if (kk >= X) {
                unsigned p = atomicAdd(&s_nc, 1u);
                if (p < 256)
                    s_cand[p] = ((unsigned long long)kk << 32) |
                                (unsigned)(0xFFFFFFFFu - (unsigned)i);
            }
        }
        __syncthreads();
    }

    // pad to 256 and bitonic sort descending (composites unique; 0-pads sink)
    int nc = min((int)s_nc, 256);
    for (int t = nc + tid; t < 256; t += TPBS) s_cand[t] = 0ull;
    __syncthreads();

    for (int ksz = 2; ksz <= 256; ksz <<= 1) {
        for (int j = ksz >> 1; j > 0; j >>= 1) {
            if (tid < 256) {
                int ixj = tid ^ j;
                if (ixj > tid) {
                    bool desc = ((tid & ksz) == 0);
                    unsigned long long a = s_cand[tid], bb = s_cand[ixj];
                    if (desc ? (a < bb) : (a > bb)) {
                        s_cand[tid] = bb;
                        s_cand[ixj] = a;
                    }
                }
            }
            __syncthreads();
        }
    }

    // emit sorted top-100 indices + exp terms (parallel expf)
    if (tid < KSEL) {
        unsigned long long comp = s_cand[tid];
        float val = fkey_inv((unsigned)(comp >> 32));
        int   idx = (int)(0xFFFFFFFFu - (unsigned)(comp & 0xFFFFFFFFu));
        g_inds[b * KSEL + tid] = idx;

        float v0 = fkey_inv((unsigned)(s_cand[0] >> 32));
        int   k  = min(max((int)sp[b * 3 + 0], 1), KSEL);
        float T  = sp[b * 3 + 2];
        float e  = (tid < k) ? expf(val / T - v0 / T) : 0.0f;
        g_exps[b * KSEL + tid] = e;
    }
}

// ---------------------------------------------------------------------------
// Kernel 3: cross-row min + top-p + median-token pick (no transcendentals)
// ---------------------------------------------------------------------------
__global__ void sample_kernel(const float* __restrict__ sp, int B,
                              float* __restrict__ out) {
    const int b = threadIdx.x;
    __shared__ float s_p0[1024];

    float S = 0.f, topp = 0.f;
    int k = 0;
    const float* e = g_exps + b * KSEL;

    if (b < B) {
        k    = min(max((int)sp[b * 3 + 0], 1), KSEL);
        topp = sp[b * 3 + 1];
        for (int i = 0; i < k; i++) S += e[i];
        s_p0[b] = 1.0f / S;           // probs[b,0] : per-row min of csum
    } else {
        s_p0[b] = 3.4e38f;
    }
    __syncthreads();

    float m = s_p0[0];
    for (int i = 1; i < B; i++) m = fminf(m, s_p0[i]);

    if (b < B) {
        float eff  = fmaxf(m, topp);
        float invS = 1.0f / S;

        float csum = 0.f, S2 = 0.f;
        int ns = 0;
        for (int i = 0; i < k; i++) {
            float ei = e[i];
            csum += ei * invS;
            if (i > 0 && csum > eff) break;
            S2 += ei;
            ns++;
        }

        float invS2 = 1.0f / S2;
        float c2 = 0.f;
        int cnt = 0;
        for (int i = 0; i < ns; i++) {
            c2 += e[i] * invS2;
            if (0.5f > c2) cnt++;
        }
        if (cnt > ns - 1) cnt = ns - 1;
        out[b] = (float)g_inds[b * KSEL + cnt];
    }
}

// ---------------------------------------------------------------------------
extern "C" void kernel_launch(void* const* d_in, const int* in_sizes, int n_in,
                              void* d_out, int out_size) {
    int li = 0, si = 1;
    if (n_in >= 2 && in_sizes[0] < in_sizes[1]) { li = 1; si = 0; }
    const float* logits = (const float*)d_in[li];
    const float* sp     = (const float*)d_in[si];
    int B = in_sizes[si] / 3;
    int V = in_sizes[li] / B;

    zero_kernel<<<1, BMAX>>>();
    dim3 gf(B, NSEGF);
    filter_kernel<<<gf, TPBF>>>(logits, V);
    select_kernel<<<B, TPBS>>>(sp, V, logits);

    int nthr = ((B + 31) / 32) * 32;
    if (nthr > 1024) nthr = 1024;
    sample_kernel<<<1, nthr>>>(sp, B, (float*)d_out);
}

// round 7
// speedup vs baseline: 4.5533x; 2.0953x over previous
#include <cuda_runtime.h>
#include <cstdint>

#define KSEL   100
#define ESTR   128          // padded exp-row stride
#define BMAX   256
#define CAP    2048
#define TPBF   256
#define QBATCH 8
#define SEGQ   (TPBF * QBATCH)   // quads per filter CTA
#define SEGCAP 128
#define TPBS   512
#define T0     8.3f         // filter threshold; exact fallback covers any input

// Scratch (__device__ globals; zero-initialized at load; g_cnt is reset by
// select_kernel every invocation so graph replays are deterministic).
__device__ int                g_cnt[BMAX];
__device__ unsigned long long g_buf[BMAX * CAP];
__device__ float              g_exps[BMAX * ESTR];
__device__ int                g_inds[BMAX * KSEL];

// Order-preserving float->uint key: bigger float => bigger key.
__device__ __forceinline__ unsigned fkey(float f) {
    unsigned u = __float_as_uint(f);
    return u ^ (unsigned)(((int)u >> 31) | 0x80000000);
}
__device__ __forceinline__ float fkey_inv(unsigned kk) {
    unsigned u = (kk & 0x80000000u) ? (kk ^ 0x80000000u) : ~kk;
    return __uint_as_float(u);
}

// ---------------------------------------------------------------------------
// Kernel 1: threshold filter. Batch-8 loads (MLP), shared compaction,
// ONE global atomic per CTA. Overflow poisons the count -> exact fallback.
// ---------------------------------------------------------------------------
__global__ __launch_bounds__(TPBF)
void filter_kernel(const float* __restrict__ logits, int V) {
    const int b   = blockIdx.x;
    const int tid = threadIdx.x;
    const float* row = logits + (size_t)b * V;
    const int V4 = V >> 2;
    const float4* r4 = (const float4*)row;
    const int s0 = blockIdx.y * SEGQ;

    __shared__ unsigned s_n;
    __shared__ int s_base;
    __shared__ unsigned long long s_loc[SEGCAP];
    if (tid == 0) s_n = 0;
    __syncthreads();

    float4 v[QBATCH];
    int    idx[QBATCH];
    bool   ok[QBATCH];
#pragma unroll
    for (int j = 0; j < QBATCH; j++) {
        idx[j] = s0 + j * TPBF + tid;
        ok[j]  = idx[j] < V4;
        if (ok[j]) v[j] = r4[idx[j]];
    }
#pragma unroll
    for (int j = 0; j < QBATCH; j++) {
        if (ok[j]) {
            float m = fmaxf(fmaxf(v[j].x, v[j].y), fmaxf(v[j].z, v[j].w));
            if (m > T0) {                          // rare (~1% of quads)
                const int base = idx[j] * 4;
                float vv[4] = {v[j].x, v[j].y, v[j].z, v[j].w};
#pragma unroll
                for (int q = 0; q < 4; q++) {
                    if (vv[q] > T0) {
                        unsigned p = atomicAdd(&s_n, 1u);
                        if (p < SEGCAP)
                            s_loc[p] = ((unsigned long long)fkey(vv[q]) << 32) |
                                       (unsigned)(0xFFFFFFFFu - (unsigned)(base + q));
                    }
                }
            }
        }
    }
    // scalar tail (V not multiple of 4) handled by segment 0
    if (blockIdx.y == 0) {
        for (int i = V4 * 4 + tid; i < V; i += TPBF) {
            float x = row[i];
            if (x > T0) {
                unsigned p = atomicAdd(&s_n, 1u);
                if (p < SEGCAP)
                    s_loc[p] = ((unsigned long long)fkey(x) << 32) |
                               (unsigned)(0xFFFFFFFFu - (unsigned)i);
            }
        }
    }
    __syncthreads();

    if (tid == 0) {
        unsigned nsu = s_n;
        int wrote = (int)min(nsu, (unsigned)SEGCAP);
        int add = (nsu > SEGCAP) ? 1000000 : wrote;   // poison -> fallback
        s_base = atomicAdd(&g_cnt[b], add);
    }
    __syncthreads();
    int ns = min((int)s_n, SEGCAP);
    unsigned long long* buf = g_buf + (size_t)b * CAP;
    for (int t = tid; t < ns; t += TPBF) {
        int pos = s_base + t;
        if (pos < CAP) buf[pos] = s_loc[t];
    }
}

// ---------------------------------------------------------------------------
// Kernel 2: per-row sort of candidates -> sorted top-100 inds + padded exps.
// Normal path: direct bitonic sort of <=512 candidates (no binary search).
// Fallback (n<100 or n>512): exact 32-pass binary search over the full row.
// ---------------------------------------------------------------------------
__global__ __launch_bounds__(TPBS)
void select_kernel(const float* __restrict__ sp, int V,
                   const float* __restrict__ logits) {
    const int b   = blockIdx.x;
    const int tid = threadIdx.x;
    const int wid  = tid >> 5;
    const int lane = tid & 31;

    __shared__ int s_part[TPBS / 32];
    __shared__ unsigned s_nc;
    __shared__ unsigned long long s_cand[512];

    const int n = g_cnt[b];
    const float* row = logits + (size_t)b * V;

    if (n >= KSEL && n <= 512) {
        const unsigned long long* buf = g_buf + (size_t)b * CAP;
        s_cand[tid] = (tid < n) ? buf[tid] : 0ull;
        __syncthreads();
    } else {
        // exact fallback: binary search on key bits over the whole row
        unsigned X = 0;
        for (int bit = 31; bit >= 0; --bit) {
            unsigned trial = X | (1u << bit);
            int local = 0;
            for (int i = tid; i < V; i += TPBS)
                local += (fkey(row[i]) >= trial);
#pragma unroll
            for (int off = 16; off; off >>= 1)
                local += __shfl_down_sync(0xffffffffu, local, off);
            if (lane == 0) s_part[wid] = local;
            __syncthreads();
            int cnt = 0;
#pragma unroll
            for (int w = 0; w < TPBS / 32; w++) cnt += s_part[w];
            __syncthreads();
            if (cnt >= KSEL) X = trial;
        }
        if (tid == 0) s_nc = 0;
        s_cand[tid] = 0ull;
        __syncthreads();
        for (int i = tid; i < V; i += TPBS) {
            unsigned kk = fkey(row[i]);
            if (kk >= X) {
                unsigned p = atomicAdd(&s_nc, 1u);
                if (p < 512)
                    s_cand[p] = ((unsigned long long)kk << 32) |
                                (unsigned)(0xFFFFFFFFu - (unsigned)i);
            }
        }
        __syncthreads();
    }

    // bitonic sort 512 desc (composites unique; 0-pads sink to the end)
    for (int ksz = 2; ksz <= 512; ksz <<= 1) {
        for (int j = ksz >> 1; j > 0; j >>= 1) {
            int ixj = tid ^ j;
            if (ixj > tid) {
                bool desc = ((tid & ksz) == 0);
                unsigned long long a = s_cand[tid], bb = s_cand[ixj];
                if (desc ? (a < bb) : (a > bb)) {
                    s_cand[tid] = bb;
                    s_cand[ixj] = a;
                }
            }
            __syncthreads();
        }
    }

    // emit sorted top-100 indices + exp terms, exps zero-padded to ESTR
    if (tid < ESTR) {
        float e = 0.f;
        if (tid < KSEL) {
            unsigned long long comp = s_cand[tid];
            float val = fkey_inv((unsigned)(comp >> 32));
            g_inds[b * KSEL + tid] =
                (int)(0xFFFFFFFFu - (unsigned)(comp & 0xFFFFFFFFu));
            float v0 = fkey_inv((unsigned)(s_cand[0] >> 32));
            int   k  = min(max((int)sp[b * 3 + 0], 1), KSEL);
            float T  = sp[b * 3 + 2];
            if (tid < k) e = expf(val / T - v0 / T);
        }
        g_exps[b * ESTR + tid] = e;
    }
    if (tid == 0) g_cnt[b] = 0;   // reset for next invocation / graph replay
}

// ---------------------------------------------------------------------------
// Kernel 3: warp-per-row sampling. Warp scan replaces serial loops.
// ---------------------------------------------------------------------------
__global__ __launch_bounds__(1024)
void sample_kernel(const float* __restrict__ sp, int B,
                   float* __restrict__ out) {
    const int tid  = threadIdx.x;
    const int w    = tid >> 5;
    const int lane = tid & 31;
    __shared__ float s_inv[1024];

    // Phase A: per-row S via warp reduce; publish 1/S
    for (int r = w; r < B; r += 32) {
        const float* e = g_exps + r * ESTR;
        float s = 0.f;
#pragma unroll
        for (int c = 0; c < 4; c++) s += e[c * 32 + lane];
#pragma unroll
        for (int off = 16; off; off >>= 1)
            s += __shfl_xor_sync(0xffffffffu, s, off);
        if (lane == 0) s_inv[r] = 1.0f / s;   // csum[r][0] = min of row csum
    }
    __syncthreads();

    // jnp.min(csum) over the whole matrix = min_b 1/S_b
    float m = s_inv[0];
    for (int i = 1; i < B; i++) m = fminf(m, s_inv[i]);

    // Phase B: per-row decision via inclusive warp scan + ballots
    for (int r = w; r < B; r += 32) {
        const float* e = g_exps + r * ESTR;
        int   k    = min(max((int)sp[r * 3 + 0], 1), KSEL);
        float topp = sp[r * 3 + 1];
        float eff  = fmaxf(m, topp);

        float p[4];
        float carry = 0.f;
#pragma unroll
        for (int c = 0; c < 4; c++) {
            float x = e[c * 32 + lane];
#pragma unroll
            for (int off = 1; off < 32; off <<= 1) {
                float y = __shfl_up_sync(0xffffffffu, x, off);
                if (lane >= off) x += y;
            }
            float pv = x + carry;
            p[c] = pv;
            carry = __shfl_sync(0xffffffffu, pv, 31);
        }
        float S = carry;                 // sum of e (zeros beyond k)
        float invS = 1.0f / S;

        // survivors = prefix {i<k : csum_i <= eff}, at least 1
        int ns = 0;
#pragma unroll
        for (int c = 0; c < 4; c++) {
            int gi = c * 32 + lane;
            bool cond = (gi < k) && (p[c] * invS <= eff);
            ns += __popc(__ballot_sync(0xffffffffu, cond));
        }
        if (ns < 1) ns = 1;

        // S2 = prefix sum at index ns-1
        int j = ns - 1, cc = j >> 5, ll = j & 31;
        float t0 = __shfl_sync(0xffffffffu, p[0], ll);
        float t1 = __shfl_sync(0xffffffffu, p[1], ll);
        float t2 = __shfl_sync(0xffffffffu, p[2], ll);
        float t3 = __shfl_sync(0xffffffffu, p[3], ll);
        float S2 = (cc == 0) ? t0 : (cc == 1) ? t1 : (cc == 2) ? t2 : t3;

        // counts = #{i<ns : prefix_i/S2 < 0.5}
        float half = 0.5f * S2;
        int cnt = 0;
#pragma unroll
        for (int c = 0; c < 4; c++) {
            int gi = c * 32 + lane;
            bool cond = (gi < ns) && (p[c] < half);
            cnt += __popc(__ballot_sync(0xffffffffu, cond));
        }
        if (cnt > ns - 1) cnt = ns - 1;
        if (cnt < 0) cnt = 0;

        if (lane == 0) out[r] = (float)g_inds[r * KSEL + cnt];
    }
}

// ---------------------------------------------------------------------------
extern "C" void kernel_launch(void* const* d_in, const int* in_sizes, int n_in,
                              void* d_out, int out_size) {
    int li = 0, si = 1;
    if (n_in >= 2 && in_sizes[0] < in_sizes[1]) { li = 1; si = 0; }
    const float* logits = (const float*)d_in[li];
    const float* sp     = (const float*)d_in[si];
    int B = in_sizes[si] / 3;
    int V = in_sizes[li] / B;

    int V4 = V >> 2;
    int nseg = (V4 + SEGQ - 1) / SEGQ;
    dim3 gf(B, nseg);
    filter_kernel<<<gf, TPBF>>>(logits, V);
    select_kernel<<<B, TPBS>>>(sp, V, logits);
    sample_kernel<<<1, 1024>>>(sp, B, (float*)d_out);
}